// round 6
// baseline (speedup 1.0000x reference)
#include <cuda_runtime.h>
#include <math.h>

// Problem constants
#define B_   32
#define H_   8
#define L_   256
#define DK_  64
#define C_   3
#define DM_  512
#define U_   30
#define KF_  131072          // H*L*DK  (flat per-batch size of K/V/Q)
#define R_   7680            // L*U     (projection rows per batch)
#define NOUT 4194304         // B*H*L*DK (cluster_center element count)

// Scratch (static device globals; no runtime allocation)
__device__ float d_Kt[(size_t)KF_ * B_];     // [kflat][b]
__device__ float d_Vt[(size_t)KF_ * B_];
__device__ float d_CKV[(size_t)R_ * 6 * B_]; // [r][{ck0,ck1,ck2,cv0,cv1,cv2}][b]
__device__ float d_CQ[L_ * 3 * B_];          // [l][c][b]
__device__ float d_CTX[L_ * 3 * B_];         // [l][c][b]
__device__ float d_MU[B_ * L_];              // [b][l]
__device__ float d_LSE[L_];                  // per-l sum over b of logsumexp(attn)

__device__ __forceinline__ float gelu_f(float x) {
    // exact erf-based GELU: x * Phi(x)
    return x * normcdff(x);
}

// ---------------------------------------------------------------------------
// Kernel A: transpose K and V from [B][KF] to [KF][B]
// ---------------------------------------------------------------------------
__global__ void transpose_kernel(const float* __restrict__ K,
                                 const float* __restrict__ V) {
    __shared__ float tile[32][33];
    const float* src = (blockIdx.y == 0) ? K : V;
    float* dst = (blockIdx.y == 0) ? d_Kt : d_Vt;
    const int kf0 = blockIdx.x * 32;
    const int tx = threadIdx.x, ty = threadIdx.y;   // (32, 8)
#pragma unroll
    for (int j = 0; j < 4; j++)
        tile[ty + 8 * j][tx] = src[(size_t)(ty + 8 * j) * KF_ + kf0 + tx];
    __syncthreads();
#pragma unroll
    for (int j = 0; j < 4; j++)
        dst[(size_t)(kf0 + ty + 8 * j) * 32 + tx] = tile[tx][ty + 8 * j];
}

// ---------------------------------------------------------------------------
// Kernel B: cq[b,l,c] = gelu(Qflat[b, l*512 : +512] . Wq[:,c] + bq[c]);
//           mu[b,l]   = mean_c cq
// One warp per (b,l) row.
// ---------------------------------------------------------------------------
__global__ void cq_kernel(const float* __restrict__ Q,
                          const float* __restrict__ Wq,
                          const float* __restrict__ bq) {
    __shared__ float swq[DM_ * 3];
    for (int i = threadIdx.x; i < DM_ * 3; i += blockDim.x) swq[i] = Wq[i];
    __syncthreads();

    const int lane = threadIdx.x & 31;
    const int w = (blockIdx.x * blockDim.x + threadIdx.x) >> 5;  // 0..8191
    const int b = w >> 8, l = w & 255;
    const float* q = Q + (size_t)b * KF_ + l * 512;

    float a0 = 0.f, a1 = 0.f, a2 = 0.f;
#pragma unroll
    for (int k = 0; k < 16; k++) {
        int m = lane + (k << 5);
        float x = q[m];
        a0 = fmaf(x, swq[m * 3 + 0], a0);
        a1 = fmaf(x, swq[m * 3 + 1], a1);
        a2 = fmaf(x, swq[m * 3 + 2], a2);
    }
#pragma unroll
    for (int off = 16; off; off >>= 1) {
        a0 += __shfl_xor_sync(0xffffffffu, a0, off);
        a1 += __shfl_xor_sync(0xffffffffu, a1, off);
        a2 += __shfl_xor_sync(0xffffffffu, a2, off);
    }
    if (lane == 0) {
        float q0 = gelu_f(a0 + bq[0]);
        float q1 = gelu_f(a1 + bq[1]);
        float q2 = gelu_f(a2 + bq[2]);
        d_CQ[(l * 3 + 0) * 32 + b] = q0;
        d_CQ[(l * 3 + 1) * 32 + b] = q1;
        d_CQ[(l * 3 + 2) * 32 + b] = q2;
        d_MU[b * 256 + l] = (q0 + q1 + q2) * (1.0f / 3.0f);
    }
}

// ---------------------------------------------------------------------------
// Kernel C: the unfold+projection. For each row r in [0, 7680):
//   ck[b,r,c] = gelu( sum_{m=0..511} Ku(b, g=r*512+m) * Wk[m,c] + bk[c] )
//   where Ku(b,g) = (b + g%30 >= 30) ? K[b + g%30 - 29, g/30] : 0
// One warp per r, lane = batch b (all 32 batches at once).
// The batch shift is a lane shift: one coalesced Kt/Vt row load per kflat,
// then __shfl_up by (29-u) for each of up to 30 inner iterations.
// ---------------------------------------------------------------------------
__global__ void ckv_kernel(const float* __restrict__ Wk, const float* __restrict__ bk,
                           const float* __restrict__ Wv, const float* __restrict__ bv) {
    __shared__ float4 swk4[DM_];   // {Wk0, Wk1, Wk2, Wv0}
    __shared__ float2 swv2[DM_];   // {Wv1, Wv2}
    for (int m = threadIdx.x; m < DM_; m += blockDim.x) {
        swk4[m] = make_float4(Wk[m * 3 + 0], Wk[m * 3 + 1], Wk[m * 3 + 2], Wv[m * 3 + 0]);
        swv2[m] = make_float2(Wv[m * 3 + 1], Wv[m * 3 + 2]);
    }
    __syncthreads();

    const int lane = threadIdx.x & 31;
    const int r = (blockIdx.x * blockDim.x + threadIdx.x) >> 5;  // 0..7679

    int g = r << 9;
    const int gend = g + 512;
    int kflat = g / 30;
    int u = g - kflat * 30;

    float a0 = 0.f, a1 = 0.f, a2 = 0.f;   // ck accumulators
    float c0 = 0.f, c1 = 0.f, c2 = 0.f;   // cv accumulators

    while (g < gend) {
        float kr = d_Kt[(size_t)kflat * 32 + lane];
        float vr = d_Vt[(size_t)kflat * 32 + lane];
        int steps = min(30 - u, gend - g);
        int m = g & 511;
        for (int s = 0; s < steps; ++s) {
            int delta = 29 - u;
            float kx = __shfl_up_sync(0xffffffffu, kr, delta);
            float vx = __shfl_up_sync(0xffffffffu, vr, delta);
            if (lane <= delta) { kx = 0.f; vx = 0.f; }   // zero-padded batches
            float4 w4 = swk4[m];
            float2 w2 = swv2[m];
            a0 = fmaf(kx, w4.x, a0);
            a1 = fmaf(kx, w4.y, a1);
            a2 = fmaf(kx, w4.z, a2);
            c0 = fmaf(vx, w4.w, c0);
            c1 = fmaf(vx, w2.x, c1);
            c2 = fmaf(vx, w2.y, c2);
            ++u; ++m;
        }
        g += steps;
        u = 0;
        ++kflat;
    }

    float* o = d_CKV + (size_t)r * 192 + lane;
    o[0]   = gelu_f(a0 + bk[0]);
    o[32]  = gelu_f(a1 + bk[1]);
    o[64]  = gelu_f(a2 + bk[2]);
    o[96]  = gelu_f(c0 + bv[0]);
    o[128] = gelu_f(c1 + bv[1]);
    o[160] = gelu_f(c2 + bv[2]);
}

// ---------------------------------------------------------------------------
// Kernel D: per (b,l): softmax over U=30, ctx = attn @ cv, lse = logsumexp(attn)
// One warp per l, lane = batch b.
// ---------------------------------------------------------------------------
__global__ void attn_kernel() {
    const int lane = threadIdx.x & 31;
    const int l = (blockIdx.x * blockDim.x + threadIdx.x) >> 5;  // 0..255

    float q0 = d_CQ[(l * 3 + 0) * 32 + lane];
    float q1 = d_CQ[(l * 3 + 1) * 32 + lane];
    float q2 = d_CQ[(l * 3 + 2) * 32 + lane];
    const float scale = 0.04419417382415922f;  // 1/sqrt(512)

    float s[30];
    float mx = -1e30f;
#pragma unroll
    for (int u = 0; u < 30; u++) {
        const float* p = d_CKV + (size_t)(l * 30 + u) * 192 + lane;
        float sc = fmaf(q0, p[0], fmaf(q1, p[32], q2 * p[64])) * scale;
        s[u] = sc;
        mx = fmaxf(mx, sc);
    }
    float sum = 0.f;
#pragma unroll
    for (int u = 0; u < 30; u++) {
        float e = expf(s[u] - mx);
        s[u] = e;
        sum += e;
    }
    float inv = 1.0f / sum;
    float x0 = 0.f, x1 = 0.f, x2 = 0.f, se = 0.f;
#pragma unroll
    for (int u = 0; u < 30; u++) {
        const float* p = d_CKV + (size_t)(l * 30 + u) * 192 + lane;
        float a = s[u] * inv;
        x0 = fmaf(a, p[96], x0);
        x1 = fmaf(a, p[128], x1);
        x2 = fmaf(a, p[160], x2);
        se += expf(a);
    }
    d_CTX[(l * 3 + 0) * 32 + lane] = x0;
    d_CTX[(l * 3 + 1) * 32 + lane] = x1;
    d_CTX[(l * 3 + 2) * 32 + lane] = x2;

    float lse = logf(se);
#pragma unroll
    for (int off = 16; off; off >>= 1)
        lse += __shfl_xor_sync(0xffffffffu, lse, off);
    if (lane == 0) d_LSE[l] = lse;   // deterministic: reduced later
}

// ---------------------------------------------------------------------------
// Kernel E: cluster_center[b, l*512+m] = gelu(ctx . Wb[:,m] + bb[m])
// One block per (b,l); 128 threads x 4 floats = 512 m values. Coalesced f4 stores.
// ---------------------------------------------------------------------------
__global__ void out_kernel(const float* __restrict__ Wb, const float* __restrict__ bb,
                           float* __restrict__ out, int out_size) {
    const int bl = blockIdx.x;                // 0..8191
    const int b = bl >> 8, l = bl & 255;
    const int m = threadIdx.x << 2;           // 0,4,...,508

    float c0 = d_CTX[(l * 3 + 0) * 32 + b];
    float c1 = d_CTX[(l * 3 + 1) * 32 + b];
    float c2 = d_CTX[(l * 3 + 2) * 32 + b];

    float4 w0 = __ldg((const float4*)(Wb + m));
    float4 w1 = __ldg((const float4*)(Wb + 512 + m));
    float4 w2 = __ldg((const float4*)(Wb + 1024 + m));
    float4 bv = __ldg((const float4*)(bb + m));

    float4 o;
    o.x = gelu_f(fmaf(c0, w0.x, fmaf(c1, w1.x, fmaf(c2, w2.x, bv.x))));
    o.y = gelu_f(fmaf(c0, w0.y, fmaf(c1, w1.y, fmaf(c2, w2.y, bv.y))));
    o.z = gelu_f(fmaf(c0, w0.z, fmaf(c1, w1.z, fmaf(c2, w2.z, bv.z))));
    o.w = gelu_f(fmaf(c0, w0.w, fmaf(c1, w1.w, fmaf(c2, w2.w, bv.w))));

    size_t idx = (size_t)b * KF_ + (size_t)l * 512 + m;
    if (idx + 4 <= (size_t)out_size)
        *(float4*)(out + idx) = o;
}

// ---------------------------------------------------------------------------
// Kernel F: the scalar loss.
//   loss = -mean_{b,l}(lse_attn) + 0.001 * ce
//   ce   = -(1/B) * sum_b [ sum_l mu^2 - lse_b * sum_l mu ],  lse_b = logsumexp_l(mu)
// One block, 32 warps (warp = batch).
// ---------------------------------------------------------------------------
__global__ void loss_kernel(float* __restrict__ out, int out_size) {
    __shared__ float terms[32];
    __shared__ float lse_tot_s;
    const int w = threadIdx.x >> 5;
    const int lane = threadIdx.x & 31;

    float v[8];
    float mx = -1e30f;
#pragma unroll
    for (int k = 0; k < 8; k++) {
        v[k] = d_MU[w * 256 + lane + (k << 5)];
        mx = fmaxf(mx, v[k]);
    }
#pragma unroll
    for (int off = 16; off; off >>= 1)
        mx = fmaxf(mx, __shfl_xor_sync(0xffffffffu, mx, off));
    float se = 0.f, sA = 0.f, sQ = 0.f;
#pragma unroll
    for (int k = 0; k < 8; k++) {
        se += expf(v[k] - mx);
        sA += v[k];
        sQ += v[k] * v[k];
    }
#pragma unroll
    for (int off = 16; off; off >>= 1) {
        se += __shfl_xor_sync(0xffffffffu, se, off);
        sA += __shfl_xor_sync(0xffffffffu, sA, off);
        sQ += __shfl_xor_sync(0xffffffffu, sQ, off);
    }
    if (lane == 0) {
        float lseb = mx + logf(se);
        terms[w] = sQ - lseb * sA;
    }
    __syncthreads();

    if (w == 0) {
        float s = 0.f;
#pragma unroll
        for (int k = 0; k < 8; k++) s += d_LSE[lane + (k << 5)];
#pragma unroll
        for (int off = 16; off; off >>= 1)
            s += __shfl_xor_sync(0xffffffffu, s, off);
        if (lane == 0) lse_tot_s = s;
    }
    __syncthreads();

    if (threadIdx.x == 0) {
        float S = 0.f;
        for (int i = 0; i < 32; i++) S += terms[i];
        float ce = -(S * (1.0f / 32.0f));
        float loss = -(lse_tot_s * (1.0f / 8192.0f)) + 0.001f * ce;
        if (out_size > NOUT) out[NOUT] = loss;
    }
}

// ---------------------------------------------------------------------------
extern "C" void kernel_launch(void* const* d_in, const int* in_sizes, int n_in,
                              void* d_out, int out_size) {
    const float* Q  = (const float*)d_in[0];
    const float* K  = (const float*)d_in[1];
    const float* V  = (const float*)d_in[2];
    const float* Wq = (const float*)d_in[3];
    const float* bq = (const float*)d_in[4];
    const float* Wk = (const float*)d_in[5];
    const float* bk = (const float*)d_in[6];
    const float* Wv = (const float*)d_in[7];
    const float* bv = (const float*)d_in[8];
    const float* Wb = (const float*)d_in[9];
    const float* bb = (const float*)d_in[10];
    float* out = (float*)d_out;

    transpose_kernel<<<dim3(KF_ / 32, 2), dim3(32, 8)>>>(K, V);
    cq_kernel<<<1024, 256>>>(Q, Wq, bq);
    ckv_kernel<<<R_ / 8, 256>>>(Wk, bk, Wv, bv);
    attn_kernel<<<32, 256>>>();
    out_kernel<<<8192, 128>>>(Wb, bb, out, out_size);
    loss_kernel<<<1, 1024>>>(out, out_size);
}

// round 7
// speedup vs baseline: 1.0065x; 1.0065x over previous
#include <cuda_runtime.h>
#include <math.h>

// Problem constants
#define B_   32
#define H_   8
#define L_   256
#define DK_  64
#define C_   3
#define DM_  512
#define U_   30
#define KF_  131072          // H*L*DK  (flat per-batch size of K/V/Q)
#define R_   7680            // L*U     (projection rows per batch)
#define NOUT 4194304         // B*H*L*DK (cluster_center element count)

// Scratch (static device globals; no runtime allocation)
__device__ float d_Kt[(size_t)KF_ * B_];     // [kflat][b]
__device__ float d_Vt[(size_t)KF_ * B_];
__device__ float d_CKV[(size_t)R_ * 6 * B_]; // [r][{ck0,ck1,ck2,cv0,cv1,cv2}][b]
__device__ float d_CQ[L_ * 3 * B_];          // [l][c][b]
__device__ float d_CTX[L_ * 3 * B_];         // [l][c][b]
__device__ float d_MU[B_ * L_];              // [b][l]
__device__ float d_LSE[L_];                  // per-l sum over b of logsumexp(attn)

__device__ __forceinline__ float gelu_f(float x) {
    // exact erf-based GELU: x * Phi(x)
    return x * normcdff(x);
}

// ---------------------------------------------------------------------------
// Kernel A: transpose K and V from [B][KF] to [KF][B]
// ---------------------------------------------------------------------------
__global__ void transpose_kernel(const float* __restrict__ K,
                                 const float* __restrict__ V) {
    __shared__ float tile[32][33];
    const float* src = (blockIdx.y == 0) ? K : V;
    float* dst = (blockIdx.y == 0) ? d_Kt : d_Vt;
    const int kf0 = blockIdx.x * 32;
    const int tx = threadIdx.x, ty = threadIdx.y;   // (32, 8)
#pragma unroll
    for (int j = 0; j < 4; j++)
        tile[ty + 8 * j][tx] = src[(size_t)(ty + 8 * j) * KF_ + kf0 + tx];
    __syncthreads();
#pragma unroll
    for (int j = 0; j < 4; j++)
        dst[(size_t)(kf0 + ty + 8 * j) * 32 + tx] = tile[tx][ty + 8 * j];
}

// ---------------------------------------------------------------------------
// Kernel B: cq[b,l,c] = gelu(Qflat[b, l*512 : +512] . Wq[:,c] + bq[c]);
//           mu[b,l]   = mean_c cq
// One warp per (b,l) row.
// ---------------------------------------------------------------------------
__global__ void cq_kernel(const float* __restrict__ Q,
                          const float* __restrict__ Wq,
                          const float* __restrict__ bq) {
    __shared__ float swq[DM_ * 3];
    for (int i = threadIdx.x; i < DM_ * 3; i += blockDim.x) swq[i] = Wq[i];
    __syncthreads();

    const int lane = threadIdx.x & 31;
    const int w = (blockIdx.x * blockDim.x + threadIdx.x) >> 5;  // 0..8191
    const int b = w >> 8, l = w & 255;
    const float* q = Q + (size_t)b * KF_ + l * 512;

    float a0 = 0.f, a1 = 0.f, a2 = 0.f;
#pragma unroll
    for (int k = 0; k < 16; k++) {
        int m = lane + (k << 5);
        float x = q[m];
        a0 = fmaf(x, swq[m * 3 + 0], a0);
        a1 = fmaf(x, swq[m * 3 + 1], a1);
        a2 = fmaf(x, swq[m * 3 + 2], a2);
    }
#pragma unroll
    for (int off = 16; off; off >>= 1) {
        a0 += __shfl_xor_sync(0xffffffffu, a0, off);
        a1 += __shfl_xor_sync(0xffffffffu, a1, off);
        a2 += __shfl_xor_sync(0xffffffffu, a2, off);
    }
    if (lane == 0) {
        float q0 = gelu_f(a0 + bq[0]);
        float q1 = gelu_f(a1 + bq[1]);
        float q2 = gelu_f(a2 + bq[2]);
        d_CQ[(l * 3 + 0) * 32 + b] = q0;
        d_CQ[(l * 3 + 1) * 32 + b] = q1;
        d_CQ[(l * 3 + 2) * 32 + b] = q2;
        d_MU[b * 256 + l] = (q0 + q1 + q2) * (1.0f / 3.0f);
    }
}

// ---------------------------------------------------------------------------
// Kernel C: the unfold+projection. For each row r in [0, 7680):
//   ck[b,r,c] = gelu( sum_{m=0..511} Ku(b, g=r*512+m) * Wk[m,c] + bk[c] )
//   where Ku(b,g) = (b + g%30 >= 30) ? K[b + g%30 - 29, g/30] : 0
// One warp per r, lane = batch b (all 32 batches at once).
// The batch shift is a lane shift: one coalesced Kt/Vt row load per kflat,
// then __shfl_up by (29-u) for each of up to 30 inner iterations.
// ---------------------------------------------------------------------------
__global__ void ckv_kernel(const float* __restrict__ Wk, const float* __restrict__ bk,
                           const float* __restrict__ Wv, const float* __restrict__ bv) {
    __shared__ float4 swk4[DM_];   // {Wk0, Wk1, Wk2, Wv0}
    __shared__ float2 swv2[DM_];   // {Wv1, Wv2}
    for (int m = threadIdx.x; m < DM_; m += blockDim.x) {
        swk4[m] = make_float4(Wk[m * 3 + 0], Wk[m * 3 + 1], Wk[m * 3 + 2], Wv[m * 3 + 0]);
        swv2[m] = make_float2(Wv[m * 3 + 1], Wv[m * 3 + 2]);
    }
    __syncthreads();

    const int lane = threadIdx.x & 31;
    const int r = (blockIdx.x * blockDim.x + threadIdx.x) >> 5;  // 0..7679

    int g = r << 9;
    const int gend = g + 512;
    int kflat = g / 30;
    int u = g - kflat * 30;

    float a0 = 0.f, a1 = 0.f, a2 = 0.f;   // ck accumulators
    float c0 = 0.f, c1 = 0.f, c2 = 0.f;   // cv accumulators

    while (g < gend) {
        float kr = d_Kt[(size_t)kflat * 32 + lane];
        float vr = d_Vt[(size_t)kflat * 32 + lane];
        int steps = min(30 - u, gend - g);
        int m = g & 511;
        for (int s = 0; s < steps; ++s) {
            int delta = 29 - u;
            float kx = __shfl_up_sync(0xffffffffu, kr, delta);
            float vx = __shfl_up_sync(0xffffffffu, vr, delta);
            if (lane <= delta) { kx = 0.f; vx = 0.f; }   // zero-padded batches
            float4 w4 = swk4[m];
            float2 w2 = swv2[m];
            a0 = fmaf(kx, w4.x, a0);
            a1 = fmaf(kx, w4.y, a1);
            a2 = fmaf(kx, w4.z, a2);
            c0 = fmaf(vx, w4.w, c0);
            c1 = fmaf(vx, w2.x, c1);
            c2 = fmaf(vx, w2.y, c2);
            ++u; ++m;
        }
        g += steps;
        u = 0;
        ++kflat;
    }

    float* o = d_CKV + (size_t)r * 192 + lane;
    o[0]   = gelu_f(a0 + bk[0]);
    o[32]  = gelu_f(a1 + bk[1]);
    o[64]  = gelu_f(a2 + bk[2]);
    o[96]  = gelu_f(c0 + bv[0]);
    o[128] = gelu_f(c1 + bv[1]);
    o[160] = gelu_f(c2 + bv[2]);
}

// ---------------------------------------------------------------------------
// Kernel D: per (b,l): softmax over U=30, ctx = attn @ cv, lse = logsumexp(attn)
// One warp per l, lane = batch b.
// ---------------------------------------------------------------------------
__global__ void attn_kernel() {
    const int lane = threadIdx.x & 31;
    const int l = (blockIdx.x * blockDim.x + threadIdx.x) >> 5;  // 0..255

    float q0 = d_CQ[(l * 3 + 0) * 32 + lane];
    float q1 = d_CQ[(l * 3 + 1) * 32 + lane];
    float q2 = d_CQ[(l * 3 + 2) * 32 + lane];
    const float scale = 0.04419417382415922f;  // 1/sqrt(512)

    float s[30];
    float mx = -1e30f;
#pragma unroll
    for (int u = 0; u < 30; u++) {
        const float* p = d_CKV + (size_t)(l * 30 + u) * 192 + lane;
        float sc = fmaf(q0, p[0], fmaf(q1, p[32], q2 * p[64])) * scale;
        s[u] = sc;
        mx = fmaxf(mx, sc);
    }
    float sum = 0.f;
#pragma unroll
    for (int u = 0; u < 30; u++) {
        float e = expf(s[u] - mx);
        s[u] = e;
        sum += e;
    }
    float inv = 1.0f / sum;
    float x0 = 0.f, x1 = 0.f, x2 = 0.f, se = 0.f;
#pragma unroll
    for (int u = 0; u < 30; u++) {
        const float* p = d_CKV + (size_t)(l * 30 + u) * 192 + lane;
        float a = s[u] * inv;
        x0 = fmaf(a, p[96], x0);
        x1 = fmaf(a, p[128], x1);
        x2 = fmaf(a, p[160], x2);
        se += expf(a);
    }
    d_CTX[(l * 3 + 0) * 32 + lane] = x0;
    d_CTX[(l * 3 + 1) * 32 + lane] = x1;
    d_CTX[(l * 3 + 2) * 32 + lane] = x2;

    float lse = logf(se);
#pragma unroll
    for (int off = 16; off; off >>= 1)
        lse += __shfl_xor_sync(0xffffffffu, lse, off);
    if (lane == 0) d_LSE[l] = lse;   // deterministic: reduced later
}

// ---------------------------------------------------------------------------
// Kernel E: cluster_center[b, l*512+m] = gelu(ctx . Wb[:,m] + bb[m])
// One block per (b,l); 128 threads x 4 floats = 512 m values. Coalesced f4 stores.
// ---------------------------------------------------------------------------
__global__ void out_kernel(const float* __restrict__ Wb, const float* __restrict__ bb,
                           float* __restrict__ out, int out_size) {
    const int bl = blockIdx.x;                // 0..8191
    const int b = bl >> 8, l = bl & 255;
    const int m = threadIdx.x << 2;           // 0,4,...,508

    float c0 = d_CTX[(l * 3 + 0) * 32 + b];
    float c1 = d_CTX[(l * 3 + 1) * 32 + b];
    float c2 = d_CTX[(l * 3 + 2) * 32 + b];

    float4 w0 = __ldg((const float4*)(Wb + m));
    float4 w1 = __ldg((const float4*)(Wb + 512 + m));
    float4 w2 = __ldg((const float4*)(Wb + 1024 + m));
    float4 bv = __ldg((const float4*)(bb + m));

    float4 o;
    o.x = gelu_f(fmaf(c0, w0.x, fmaf(c1, w1.x, fmaf(c2, w2.x, bv.x))));
    o.y = gelu_f(fmaf(c0, w0.y, fmaf(c1, w1.y, fmaf(c2, w2.y, bv.y))));
    o.z = gelu_f(fmaf(c0, w0.z, fmaf(c1, w1.z, fmaf(c2, w2.z, bv.z))));
    o.w = gelu_f(fmaf(c0, w0.w, fmaf(c1, w1.w, fmaf(c2, w2.w, bv.w))));

    size_t idx = (size_t)b * KF_ + (size_t)l * 512 + m;
    if (idx + 4 <= (size_t)out_size)
        *(float4*)(out + idx) = o;
}

// ---------------------------------------------------------------------------
// Kernel F: the scalar loss.
//   loss = -mean_{b,l}(lse_attn) + 0.001 * ce
//   ce   = -(1/B) * sum_b [ sum_l mu^2 - lse_b * sum_l mu ],  lse_b = logsumexp_l(mu)
// One block, 32 warps (warp = batch).
// ---------------------------------------------------------------------------
__global__ void loss_kernel(float* __restrict__ out, int out_size) {
    __shared__ float terms[32];
    __shared__ float lse_tot_s;
    const int w = threadIdx.x >> 5;
    const int lane = threadIdx.x & 31;

    float v[8];
    float mx = -1e30f;
#pragma unroll
    for (int k = 0; k < 8; k++) {
        v[k] = d_MU[w * 256 + lane + (k << 5)];
        mx = fmaxf(mx, v[k]);
    }
#pragma unroll
    for (int off = 16; off; off >>= 1)
        mx = fmaxf(mx, __shfl_xor_sync(0xffffffffu, mx, off));
    float se = 0.f, sA = 0.f, sQ = 0.f;
#pragma unroll
    for (int k = 0; k < 8; k++) {
        se += expf(v[k] - mx);
        sA += v[k];
        sQ += v[k] * v[k];
    }
#pragma unroll
    for (int off = 16; off; off >>= 1) {
        se += __shfl_xor_sync(0xffffffffu, se, off);
        sA += __shfl_xor_sync(0xffffffffu, sA, off);
        sQ += __shfl_xor_sync(0xffffffffu, sQ, off);
    }
    if (lane == 0) {
        float lseb = mx + logf(se);
        terms[w] = sQ - lseb * sA;
    }
    __syncthreads();

    if (w == 0) {
        float s = 0.f;
#pragma unroll
        for (int k = 0; k < 8; k++) s += d_LSE[lane + (k << 5)];
#pragma unroll
        for (int off = 16; off; off >>= 1)
            s += __shfl_xor_sync(0xffffffffu, s, off);
        if (lane == 0) lse_tot_s = s;
    }
    __syncthreads();

    if (threadIdx.x == 0) {
        float S = 0.f;
        for (int i = 0; i < 32; i++) S += terms[i];
        float ce = -(S * (1.0f / 32.0f));
        float loss = -(lse_tot_s * (1.0f / 8192.0f)) + 0.001f * ce;
        if (out_size > NOUT) out[NOUT] = loss;
    }
}

// ---------------------------------------------------------------------------
extern "C" void kernel_launch(void* const* d_in, const int* in_sizes, int n_in,
                              void* d_out, int out_size) {
    const float* Q  = (const float*)d_in[0];
    const float* K  = (const float*)d_in[1];
    const float* V  = (const float*)d_in[2];
    const float* Wq = (const float*)d_in[3];
    const float* bq = (const float*)d_in[4];
    const float* Wk = (const float*)d_in[5];
    const float* bk = (const float*)d_in[6];
    const float* Wv = (const float*)d_in[7];
    const float* bv = (const float*)d_in[8];
    const float* Wb = (const float*)d_in[9];
    const float* bb = (const float*)d_in[10];
    float* out = (float*)d_out;

    transpose_kernel<<<dim3(KF_ / 32, 2), dim3(32, 8)>>>(K, V);
    cq_kernel<<<1024, 256>>>(Q, Wq, bq);
    ckv_kernel<<<R_ / 8, 256>>>(Wk, bk, Wv, bv);
    attn_kernel<<<32, 256>>>();
    out_kernel<<<8192, 128>>>(Wb, bb, out, out_size);
    loss_kernel<<<1, 1024>>>(out, out_size);
}

// round 8
// speedup vs baseline: 1.1086x; 1.1015x over previous
#include <cuda_runtime.h>
#include <math.h>

// Problem constants
#define B_   32
#define H_   8
#define L_   256
#define DK_  64
#define C_   3
#define DM_  512
#define U_   30
#define KF_  131072          // H*L*DK  (flat per-batch size of K/V/Q)
#define R_   7680            // L*U     (projection rows per batch)
#define NOUT 4194304         // B*H*L*DK (cluster_center element count)

// Scratch (static device globals; no runtime allocation)
__device__ float2 d_KVt[(size_t)KF_ * B_];   // [kflat][b] -> (K, V) interleaved
__device__ float  d_CKV[(size_t)R_ * B_ * 8];// [r][b][{ck0,ck1,ck2,_,cv0,cv1,cv2,_}]
__device__ float  d_CQ[L_ * 3 * B_];         // [l][c][b]
__device__ float  d_CTX[L_ * 3 * B_];        // [l][c][b]
__device__ float  d_MU[B_ * L_];             // [b][l]
__device__ float  d_LSE[L_];                 // per-l sum over b of logsumexp(attn)

__device__ __forceinline__ float gelu_f(float x) {
    return x * normcdff(x);    // exact erf-based GELU
}

__device__ __forceinline__ unsigned long long pack2(float a, float b) {
    unsigned long long r;
    asm("mov.b64 %0, {%1, %2};" : "=l"(r) : "f"(a), "f"(b));
    return r;
}
__device__ __forceinline__ float2 unpack2(unsigned long long v) {
    float2 f;
    asm("mov.b64 {%0, %1}, %2;" : "=f"(f.x), "=f"(f.y) : "l"(v));
    return f;
}
#define FFMA2(acc, a, b) \
    asm("fma.rn.f32x2 %0, %1, %2, %0;" : "+l"(acc) : "l"(a), "l"(b))

// ---------------------------------------------------------------------------
// Kernel A: transpose K,V from [B][KF] to interleaved [KF][B] float2
// ---------------------------------------------------------------------------
__global__ void transpose_kernel(const float* __restrict__ K,
                                 const float* __restrict__ V) {
    __shared__ float tk[32][33], tv[32][33];
    const int kf0 = blockIdx.x * 32;
    const int tx = threadIdx.x, ty = threadIdx.y;   // (32, 8)
#pragma unroll
    for (int j = 0; j < 4; j++) {
        tk[ty + 8 * j][tx] = K[(size_t)(ty + 8 * j) * KF_ + kf0 + tx];
        tv[ty + 8 * j][tx] = V[(size_t)(ty + 8 * j) * KF_ + kf0 + tx];
    }
    __syncthreads();
#pragma unroll
    for (int j = 0; j < 4; j++) {
        int row = ty + 8 * j;
        d_KVt[(size_t)(kf0 + row) * 32 + tx] = make_float2(tk[tx][row], tv[tx][row]);
    }
}

// ---------------------------------------------------------------------------
// Kernel B: cq[b,l,c] = gelu(Qflat[b, l*512 : +512] . Wq[:,c] + bq[c]);
//           mu[b,l]   = mean_c cq.   One warp per (b,l).
// ---------------------------------------------------------------------------
__global__ void cq_kernel(const float* __restrict__ Q,
                          const float* __restrict__ Wq,
                          const float* __restrict__ bq) {
    __shared__ float swq[DM_ * 3];
    for (int i = threadIdx.x; i < DM_ * 3; i += blockDim.x) swq[i] = Wq[i];
    __syncthreads();

    const int lane = threadIdx.x & 31;
    const int w = (blockIdx.x * blockDim.x + threadIdx.x) >> 5;  // 0..8191
    const int b = w >> 8, l = w & 255;
    const float* q = Q + (size_t)b * KF_ + l * 512;

    float a0 = 0.f, a1 = 0.f, a2 = 0.f;
#pragma unroll
    for (int k = 0; k < 16; k++) {
        int m = lane + (k << 5);
        float x = q[m];
        a0 = fmaf(x, swq[m * 3 + 0], a0);
        a1 = fmaf(x, swq[m * 3 + 1], a1);
        a2 = fmaf(x, swq[m * 3 + 2], a2);
    }
#pragma unroll
    for (int off = 16; off; off >>= 1) {
        a0 += __shfl_xor_sync(0xffffffffu, a0, off);
        a1 += __shfl_xor_sync(0xffffffffu, a1, off);
        a2 += __shfl_xor_sync(0xffffffffu, a2, off);
    }
    if (lane == 0) {
        float q0 = gelu_f(a0 + bq[0]);
        float q1 = gelu_f(a1 + bq[1]);
        float q2 = gelu_f(a2 + bq[2]);
        d_CQ[(l * 3 + 0) * 32 + b] = q0;
        d_CQ[(l * 3 + 1) * 32 + b] = q1;
        d_CQ[(l * 3 + 2) * 32 + b] = q2;
        d_MU[b * 256 + l] = (q0 + q1 + q2) * (1.0f / 3.0f);
    }
}

// ---------------------------------------------------------------------------
// Kernel C: unfold+projection, shuffle-free.
// For row r, element g = r*512+m uses weight W[m] and data
//   Kpad[lane + u, kflat]  (kflat=g/30, u=g%30)  = row_kflat[lane-(29-u)],
//   zero when lane <= 29-u.  We stage each interleaved KV row into a per-warp
//   zero-padded smem buffer P:  P[0..32]=0, P[32+t]=row[t] (t>=1; row[0] is
//   never a valid source).  Then the per-step value for all 32 batches is a
//   single conflict-free LDS.64 at P[3 + lane + u], index +1 per step.
// Math uses packed f32x2 FMA: lo lane = K path, hi lane = V path.
// ---------------------------------------------------------------------------
__global__ void ckv_kernel(const float* __restrict__ Wk, const float* __restrict__ bk,
                           const float* __restrict__ Wv, const float* __restrict__ bv) {
    __shared__ ulonglong2 swA[DM_];          // {(wk0,wv0),(wk1,wv1)} per m
    __shared__ unsigned long long swB[DM_];  // (wk2,wv2) per m
    __shared__ float2 spad[8][64];           // per-warp padded KV row

    for (int m = threadIdx.x; m < DM_; m += blockDim.x) {
        ulonglong2 a;
        a.x = pack2(Wk[m * 3 + 0], Wv[m * 3 + 0]);
        a.y = pack2(Wk[m * 3 + 1], Wv[m * 3 + 1]);
        swA[m] = a;
        swB[m] = pack2(Wk[m * 3 + 2], Wv[m * 3 + 2]);
    }
    const int lane = threadIdx.x & 31;
    const int wid = threadIdx.x >> 5;
    float2* P = spad[wid];
    P[lane] = make_float2(0.f, 0.f);
    if (lane == 0) P[32] = make_float2(0.f, 0.f);
    __syncthreads();

    const int r = (blockIdx.x * blockDim.x + threadIdx.x) >> 5;  // 0..7679
    int g = r << 9;
    const int gend = g + 512;
    int kflat = g / 30;
    int u = g - kflat * 30;

    unsigned long long acc0 = 0ull, acc1 = 0ull, acc2 = 0ull;  // (0.f, 0.f)

    while (g < gend) {
        float2 kv = d_KVt[(size_t)kflat * 32 + lane];
        if (lane == 0) kv = make_float2(0.f, 0.f);   // row[0] is the zero pad
        __syncwarp();
        P[32 + lane] = kv;
        __syncwarp();
        int steps = min(30 - u, gend - g);
        const unsigned long long* pd =
            (const unsigned long long*)(P + 3 + u) + lane;
        const ulonglong2* pa = swA + (g & 511);
        const unsigned long long* pb = swB + (g & 511);
        for (int s = 0; s < steps; ++s) {
            unsigned long long kvx = pd[s];
            ulonglong2 w01 = pa[s];
            unsigned long long w2 = pb[s];
            FFMA2(acc0, kvx, w01.x);
            FFMA2(acc1, kvx, w01.y);
            FFMA2(acc2, kvx, w2);
        }
        g += steps;
        u = 0;
        ++kflat;
    }

    float2 r0 = unpack2(acc0), r1 = unpack2(acc1), r2 = unpack2(acc2);
    float4 ck4, cv4;
    ck4.x = gelu_f(r0.x + bk[0]);
    ck4.y = gelu_f(r1.x + bk[1]);
    ck4.z = gelu_f(r2.x + bk[2]);
    ck4.w = 0.f;
    cv4.x = gelu_f(r0.y + bv[0]);
    cv4.y = gelu_f(r1.y + bv[1]);
    cv4.z = gelu_f(r2.y + bv[2]);
    cv4.w = 0.f;
    float4* o = (float4*)(d_CKV + ((size_t)r * 32 + lane) * 8);
    o[0] = ck4;
    o[1] = cv4;
}

// ---------------------------------------------------------------------------
// Kernel D: per (b,l): softmax over U=30, ctx = attn @ cv, lse = logsumexp(attn)
// One single-warp block per l (max SM spread); lane = batch b.
// d_CKV layout gives one LDG.128 per u per pass.
// ---------------------------------------------------------------------------
__global__ void attn_kernel() {
    const int lane = threadIdx.x;   // 32-thread blocks
    const int l = blockIdx.x;       // 0..255

    float q0 = d_CQ[(l * 3 + 0) * 32 + lane];
    float q1 = d_CQ[(l * 3 + 1) * 32 + lane];
    float q2 = d_CQ[(l * 3 + 2) * 32 + lane];
    const float scale = 0.04419417382415922f;  // 1/sqrt(512)

    const float4* base = (const float4*)(d_CKV + ((size_t)l * 30) * 32 * 8) + lane * 2;

    float s[30];
    float mx = -1e30f;
#pragma unroll
    for (int u = 0; u < 30; u++) {
        float4 t = base[u * 64];     // {ck0,ck1,ck2,_}
        float sc = fmaf(q0, t.x, fmaf(q1, t.y, q2 * t.z)) * scale;
        s[u] = sc;
        mx = fmaxf(mx, sc);
    }
    float sum = 0.f;
#pragma unroll
    for (int u = 0; u < 30; u++) {
        float e = expf(s[u] - mx);
        s[u] = e;
        sum += e;
    }
    float inv = 1.0f / sum;
    float x0 = 0.f, x1 = 0.f, x2 = 0.f, se = 0.f;
#pragma unroll
    for (int u = 0; u < 30; u++) {
        float4 t = base[u * 64 + 1]; // {cv0,cv1,cv2,_}
        float a = s[u] * inv;
        x0 = fmaf(a, t.x, x0);
        x1 = fmaf(a, t.y, x1);
        x2 = fmaf(a, t.z, x2);
        se += expf(a);
    }
    d_CTX[(l * 3 + 0) * 32 + lane] = x0;
    d_CTX[(l * 3 + 1) * 32 + lane] = x1;
    d_CTX[(l * 3 + 2) * 32 + lane] = x2;

    float lse = logf(se);
#pragma unroll
    for (int off = 16; off; off >>= 1)
        lse += __shfl_xor_sync(0xffffffffu, lse, off);
    if (lane == 0) d_LSE[l] = lse;
}

// ---------------------------------------------------------------------------
// Kernel E: cluster_center[b, l*512+m] = gelu(ctx . Wb[:,m] + bb[m])
// ---------------------------------------------------------------------------
__global__ void out_kernel(const float* __restrict__ Wb, const float* __restrict__ bb,
                           float* __restrict__ out, int out_size) {
    const int bl = blockIdx.x;                // 0..8191
    const int b = bl >> 8, l = bl & 255;
    const int m = threadIdx.x << 2;           // 0,4,...,508

    float c0 = d_CTX[(l * 3 + 0) * 32 + b];
    float c1 = d_CTX[(l * 3 + 1) * 32 + b];
    float c2 = d_CTX[(l * 3 + 2) * 32 + b];

    float4 w0 = __ldg((const float4*)(Wb + m));
    float4 w1 = __ldg((const float4*)(Wb + 512 + m));
    float4 w2 = __ldg((const float4*)(Wb + 1024 + m));
    float4 bv = __ldg((const float4*)(bb + m));

    float4 o;
    o.x = gelu_f(fmaf(c0, w0.x, fmaf(c1, w1.x, fmaf(c2, w2.x, bv.x))));
    o.y = gelu_f(fmaf(c0, w0.y, fmaf(c1, w1.y, fmaf(c2, w2.y, bv.y))));
    o.z = gelu_f(fmaf(c0, w0.z, fmaf(c1, w1.z, fmaf(c2, w2.z, bv.z))));
    o.w = gelu_f(fmaf(c0, w0.w, fmaf(c1, w1.w, fmaf(c2, w2.w, bv.w))));

    size_t idx = (size_t)b * KF_ + (size_t)l * 512 + m;
    if (idx + 4 <= (size_t)out_size)
        *(float4*)(out + idx) = o;
}

// ---------------------------------------------------------------------------
// Kernel F: the scalar loss.
// ---------------------------------------------------------------------------
__global__ void loss_kernel(float* __restrict__ out, int out_size) {
    __shared__ float terms[32];
    __shared__ float lse_tot_s;
    const int w = threadIdx.x >> 5;
    const int lane = threadIdx.x & 31;

    float v[8];
    float mx = -1e30f;
#pragma unroll
    for (int k = 0; k < 8; k++) {
        v[k] = d_MU[w * 256 + lane + (k << 5)];
        mx = fmaxf(mx, v[k]);
    }
#pragma unroll
    for (int off = 16; off; off >>= 1)
        mx = fmaxf(mx, __shfl_xor_sync(0xffffffffu, mx, off));
    float se = 0.f, sA = 0.f, sQ = 0.f;
#pragma unroll
    for (int k = 0; k < 8; k++) {
        se += expf(v[k] - mx);
        sA += v[k];
        sQ += v[k] * v[k];
    }
#pragma unroll
    for (int off = 16; off; off >>= 1) {
        se += __shfl_xor_sync(0xffffffffu, se, off);
        sA += __shfl_xor_sync(0xffffffffu, sA, off);
        sQ += __shfl_xor_sync(0xffffffffu, sQ, off);
    }
    if (lane == 0) {
        float lseb = mx + logf(se);
        terms[w] = sQ - lseb * sA;
    }
    __syncthreads();

    if (w == 0) {
        float s = 0.f;
#pragma unroll
        for (int k = 0; k < 8; k++) s += d_LSE[lane + (k << 5)];
#pragma unroll
        for (int off = 16; off; off >>= 1)
            s += __shfl_xor_sync(0xffffffffu, s, off);
        if (lane == 0) lse_tot_s = s;
    }
    __syncthreads();

    if (threadIdx.x == 0) {
        float S = 0.f;
        for (int i = 0; i < 32; i++) S += terms[i];
        float ce = -(S * (1.0f / 32.0f));
        float loss = -(lse_tot_s * (1.0f / 8192.0f)) + 0.001f * ce;
        if (out_size > NOUT) out[NOUT] = loss;
    }
}

// ---------------------------------------------------------------------------
extern "C" void kernel_launch(void* const* d_in, const int* in_sizes, int n_in,
                              void* d_out, int out_size) {
    const float* Q  = (const float*)d_in[0];
    const float* K  = (const float*)d_in[1];
    const float* V  = (const float*)d_in[2];
    const float* Wq = (const float*)d_in[3];
    const float* bq = (const float*)d_in[4];
    const float* Wk = (const float*)d_in[5];
    const float* bk = (const float*)d_in[6];
    const float* Wv = (const float*)d_in[7];
    const float* bv = (const float*)d_in[8];
    const float* Wb = (const float*)d_in[9];
    const float* bb = (const float*)d_in[10];
    float* out = (float*)d_out;

    transpose_kernel<<<KF_ / 32, dim3(32, 8)>>>(K, V);
    cq_kernel<<<1024, 256>>>(Q, Wq, bq);
    ckv_kernel<<<R_ / 8, 256>>>(Wk, bk, Wv, bv);
    attn_kernel<<<256, 32>>>();
    out_kernel<<<8192, 128>>>(Wb, bb, out, out_size);
    loss_kernel<<<1, 1024>>>(out, out_size);
}

// round 9
// speedup vs baseline: 1.1101x; 1.0013x over previous
#include <cuda_runtime.h>
#include <math.h>

// Problem constants
#define B_   32
#define H_   8
#define L_   256
#define DK_  64
#define C_   3
#define DM_  512
#define U_   30
#define KF_  131072          // H*L*DK  (flat per-batch size of K/V/Q)
#define R_   7680            // L*U     (projection rows per batch)
#define NOUT 4194304         // B*H*L*DK (cluster_center element count)

// Scratch (static device globals; no runtime allocation)
__device__ float2 d_KVt[(size_t)KF_ * B_];   // [kflat][b] -> (K, V) interleaved
__device__ float  d_CKV[(size_t)R_ * B_ * 8];// [r][b][{ck0,ck1,ck2,_,cv0,cv1,cv2,_}]
__device__ float  d_CQ[L_ * 3 * B_];         // [l][c][b]
__device__ float  d_CTX[L_ * 3 * B_];        // [l][c][b]
__device__ float  d_MU[B_ * L_];             // [b][l]
__device__ float  d_LSE[L_];                 // per-l sum over b of logsumexp(attn)

__device__ __forceinline__ float gelu_f(float x) {
    return x * normcdff(x);    // exact erf-based GELU
}

__device__ __forceinline__ unsigned long long pack2(float a, float b) {
    unsigned long long r;
    asm("mov.b64 %0, {%1, %2};" : "=l"(r) : "f"(a), "f"(b));
    return r;
}
__device__ __forceinline__ float2 unpack2(unsigned long long v) {
    float2 f;
    asm("mov.b64 {%0, %1}, %2;" : "=f"(f.x), "=f"(f.y) : "l"(v));
    return f;
}
#define FFMA2(acc, a, b) \
    asm("fma.rn.f32x2 %0, %1, %2, %0;" : "+l"(acc) : "l"(a), "l"(b))

// ---------------------------------------------------------------------------
// Kernel A: transpose K,V from [B][KF] to interleaved [KF][B] float2
// ---------------------------------------------------------------------------
__global__ void transpose_kernel(const float* __restrict__ K,
                                 const float* __restrict__ V) {
    __shared__ float tk[32][33], tv[32][33];
    const int kf0 = blockIdx.x * 32;
    const int tx = threadIdx.x, ty = threadIdx.y;   // (32, 8)
#pragma unroll
    for (int j = 0; j < 4; j++) {
        tk[ty + 8 * j][tx] = K[(size_t)(ty + 8 * j) * KF_ + kf0 + tx];
        tv[ty + 8 * j][tx] = V[(size_t)(ty + 8 * j) * KF_ + kf0 + tx];
    }
    __syncthreads();
#pragma unroll
    for (int j = 0; j < 4; j++) {
        int row = ty + 8 * j;
        d_KVt[(size_t)(kf0 + row) * 32 + tx] = make_float2(tk[tx][row], tv[tx][row]);
    }
}

// ---------------------------------------------------------------------------
// Kernel B: cq[b,l,c] = gelu(Qflat[b, l*512 : +512] . Wq[:,c] + bq[c]);
//           mu[b,l]   = mean_c cq.   One warp per (b,l).
// ---------------------------------------------------------------------------
__global__ void cq_kernel(const float* __restrict__ Q,
                          const float* __restrict__ Wq,
                          const float* __restrict__ bq) {
    __shared__ float swq[DM_ * 3];
    for (int i = threadIdx.x; i < DM_ * 3; i += blockDim.x) swq[i] = Wq[i];
    __syncthreads();

    const int lane = threadIdx.x & 31;
    const int w = (blockIdx.x * blockDim.x + threadIdx.x) >> 5;  // 0..8191
    const int b = w >> 8, l = w & 255;
    const float* q = Q + (size_t)b * KF_ + l * 512;

    float a0 = 0.f, a1 = 0.f, a2 = 0.f;
#pragma unroll
    for (int k = 0; k < 16; k++) {
        int m = lane + (k << 5);
        float x = q[m];
        a0 = fmaf(x, swq[m * 3 + 0], a0);
        a1 = fmaf(x, swq[m * 3 + 1], a1);
        a2 = fmaf(x, swq[m * 3 + 2], a2);
    }
#pragma unroll
    for (int off = 16; off; off >>= 1) {
        a0 += __shfl_xor_sync(0xffffffffu, a0, off);
        a1 += __shfl_xor_sync(0xffffffffu, a1, off);
        a2 += __shfl_xor_sync(0xffffffffu, a2, off);
    }
    if (lane == 0) {
        float q0 = gelu_f(a0 + bq[0]);
        float q1 = gelu_f(a1 + bq[1]);
        float q2 = gelu_f(a2 + bq[2]);
        d_CQ[(l * 3 + 0) * 32 + b] = q0;
        d_CQ[(l * 3 + 1) * 32 + b] = q1;
        d_CQ[(l * 3 + 2) * 32 + b] = q2;
        d_MU[b * 256 + l] = (q0 + q1 + q2) * (1.0f / 3.0f);
    }
}

// ---------------------------------------------------------------------------
// Kernel C: unfold+projection, shuffle-free.
// For row r, element g = r*512+m uses weight W[m] and data
//   Kpad[lane + u, kflat]  (kflat=g/30, u=g%30)  = row_kflat[lane-(29-u)],
//   zero when lane <= 29-u.  We stage each interleaved KV row into a per-warp
//   zero-padded smem buffer P:  P[0..32]=0, P[32+t]=row[t] (t>=1; row[0] is
//   never a valid source).  Then the per-step value for all 32 batches is a
//   single conflict-free LDS.64 at P[3 + lane + u], index +1 per step.
// Math uses packed f32x2 FMA: lo lane = K path, hi lane = V path.
// ---------------------------------------------------------------------------
__global__ void ckv_kernel(const float* __restrict__ Wk, const float* __restrict__ bk,
                           const float* __restrict__ Wv, const float* __restrict__ bv) {
    __shared__ ulonglong2 swA[DM_];          // {(wk0,wv0),(wk1,wv1)} per m
    __shared__ unsigned long long swB[DM_];  // (wk2,wv2) per m
    __shared__ float2 spad[8][64];           // per-warp padded KV row

    for (int m = threadIdx.x; m < DM_; m += blockDim.x) {
        ulonglong2 a;
        a.x = pack2(Wk[m * 3 + 0], Wv[m * 3 + 0]);
        a.y = pack2(Wk[m * 3 + 1], Wv[m * 3 + 1]);
        swA[m] = a;
        swB[m] = pack2(Wk[m * 3 + 2], Wv[m * 3 + 2]);
    }
    const int lane = threadIdx.x & 31;
    const int wid = threadIdx.x >> 5;
    float2* P = spad[wid];
    P[lane] = make_float2(0.f, 0.f);
    if (lane == 0) P[32] = make_float2(0.f, 0.f);
    __syncthreads();

    const int r = (blockIdx.x * blockDim.x + threadIdx.x) >> 5;  // 0..7679
    int g = r << 9;
    const int gend = g + 512;
    int kflat = g / 30;
    int u = g - kflat * 30;

    unsigned long long acc0 = 0ull, acc1 = 0ull, acc2 = 0ull;  // (0.f, 0.f)

    while (g < gend) {
        float2 kv = d_KVt[(size_t)kflat * 32 + lane];
        if (lane == 0) kv = make_float2(0.f, 0.f);   // row[0] is the zero pad
        __syncwarp();
        P[32 + lane] = kv;
        __syncwarp();
        int steps = min(30 - u, gend - g);
        const unsigned long long* pd =
            (const unsigned long long*)(P + 3 + u) + lane;
        const ulonglong2* pa = swA + (g & 511);
        const unsigned long long* pb = swB + (g & 511);
        for (int s = 0; s < steps; ++s) {
            unsigned long long kvx = pd[s];
            ulonglong2 w01 = pa[s];
            unsigned long long w2 = pb[s];
            FFMA2(acc0, kvx, w01.x);
            FFMA2(acc1, kvx, w01.y);
            FFMA2(acc2, kvx, w2);
        }
        g += steps;
        u = 0;
        ++kflat;
    }

    float2 r0 = unpack2(acc0), r1 = unpack2(acc1), r2 = unpack2(acc2);
    float4 ck4, cv4;
    ck4.x = gelu_f(r0.x + bk[0]);
    ck4.y = gelu_f(r1.x + bk[1]);
    ck4.z = gelu_f(r2.x + bk[2]);
    ck4.w = 0.f;
    cv4.x = gelu_f(r0.y + bv[0]);
    cv4.y = gelu_f(r1.y + bv[1]);
    cv4.z = gelu_f(r2.y + bv[2]);
    cv4.w = 0.f;
    float4* o = (float4*)(d_CKV + ((size_t)r * 32 + lane) * 8);
    o[0] = ck4;
    o[1] = cv4;
}

// ---------------------------------------------------------------------------
// Kernel D: per (b,l): softmax over U=30, ctx = attn @ cv, lse = logsumexp(attn)
// One single-warp block per l (max SM spread); lane = batch b.
// d_CKV layout gives one LDG.128 per u per pass.
// ---------------------------------------------------------------------------
__global__ void attn_kernel() {
    const int lane = threadIdx.x;   // 32-thread blocks
    const int l = blockIdx.x;       // 0..255

    float q0 = d_CQ[(l * 3 + 0) * 32 + lane];
    float q1 = d_CQ[(l * 3 + 1) * 32 + lane];
    float q2 = d_CQ[(l * 3 + 2) * 32 + lane];
    const float scale = 0.04419417382415922f;  // 1/sqrt(512)

    const float4* base = (const float4*)(d_CKV + ((size_t)l * 30) * 32 * 8) + lane * 2;

    float s[30];
    float mx = -1e30f;
#pragma unroll
    for (int u = 0; u < 30; u++) {
        float4 t = base[u * 64];     // {ck0,ck1,ck2,_}
        float sc = fmaf(q0, t.x, fmaf(q1, t.y, q2 * t.z)) * scale;
        s[u] = sc;
        mx = fmaxf(mx, sc);
    }
    float sum = 0.f;
#pragma unroll
    for (int u = 0; u < 30; u++) {
        float e = expf(s[u] - mx);
        s[u] = e;
        sum += e;
    }
    float inv = 1.0f / sum;
    float x0 = 0.f, x1 = 0.f, x2 = 0.f, se = 0.f;
#pragma unroll
    for (int u = 0; u < 30; u++) {
        float4 t = base[u * 64 + 1]; // {cv0,cv1,cv2,_}
        float a = s[u] * inv;
        x0 = fmaf(a, t.x, x0);
        x1 = fmaf(a, t.y, x1);
        x2 = fmaf(a, t.z, x2);
        se += expf(a);
    }
    d_CTX[(l * 3 + 0) * 32 + lane] = x0;
    d_CTX[(l * 3 + 1) * 32 + lane] = x1;
    d_CTX[(l * 3 + 2) * 32 + lane] = x2;

    float lse = logf(se);
#pragma unroll
    for (int off = 16; off; off >>= 1)
        lse += __shfl_xor_sync(0xffffffffu, lse, off);
    if (lane == 0) d_LSE[l] = lse;
}

// ---------------------------------------------------------------------------
// Kernel E: cluster_center[b, l*512+m] = gelu(ctx . Wb[:,m] + bb[m])
// ---------------------------------------------------------------------------
__global__ void out_kernel(const float* __restrict__ Wb, const float* __restrict__ bb,
                           float* __restrict__ out, int out_size) {
    const int bl = blockIdx.x;                // 0..8191
    const int b = bl >> 8, l = bl & 255;
    const int m = threadIdx.x << 2;           // 0,4,...,508

    float c0 = d_CTX[(l * 3 + 0) * 32 + b];
    float c1 = d_CTX[(l * 3 + 1) * 32 + b];
    float c2 = d_CTX[(l * 3 + 2) * 32 + b];

    float4 w0 = __ldg((const float4*)(Wb + m));
    float4 w1 = __ldg((const float4*)(Wb + 512 + m));
    float4 w2 = __ldg((const float4*)(Wb + 1024 + m));
    float4 bv = __ldg((const float4*)(bb + m));

    float4 o;
    o.x = gelu_f(fmaf(c0, w0.x, fmaf(c1, w1.x, fmaf(c2, w2.x, bv.x))));
    o.y = gelu_f(fmaf(c0, w0.y, fmaf(c1, w1.y, fmaf(c2, w2.y, bv.y))));
    o.z = gelu_f(fmaf(c0, w0.z, fmaf(c1, w1.z, fmaf(c2, w2.z, bv.z))));
    o.w = gelu_f(fmaf(c0, w0.w, fmaf(c1, w1.w, fmaf(c2, w2.w, bv.w))));

    size_t idx = (size_t)b * KF_ + (size_t)l * 512 + m;
    if (idx + 4 <= (size_t)out_size)
        *(float4*)(out + idx) = o;
}

// ---------------------------------------------------------------------------
// Kernel F: the scalar loss.
// ---------------------------------------------------------------------------
__global__ void loss_kernel(float* __restrict__ out, int out_size) {
    __shared__ float terms[32];
    __shared__ float lse_tot_s;
    const int w = threadIdx.x >> 5;
    const int lane = threadIdx.x & 31;

    float v[8];
    float mx = -1e30f;
#pragma unroll
    for (int k = 0; k < 8; k++) {
        v[k] = d_MU[w * 256 + lane + (k << 5)];
        mx = fmaxf(mx, v[k]);
    }
#pragma unroll
    for (int off = 16; off; off >>= 1)
        mx = fmaxf(mx, __shfl_xor_sync(0xffffffffu, mx, off));
    float se = 0.f, sA = 0.f, sQ = 0.f;
#pragma unroll
    for (int k = 0; k < 8; k++) {
        se += expf(v[k] - mx);
        sA += v[k];
        sQ += v[k] * v[k];
    }
#pragma unroll
    for (int off = 16; off; off >>= 1) {
        se += __shfl_xor_sync(0xffffffffu, se, off);
        sA += __shfl_xor_sync(0xffffffffu, sA, off);
        sQ += __shfl_xor_sync(0xffffffffu, sQ, off);
    }
    if (lane == 0) {
        float lseb = mx + logf(se);
        terms[w] = sQ - lseb * sA;
    }
    __syncthreads();

    if (w == 0) {
        float s = 0.f;
#pragma unroll
        for (int k = 0; k < 8; k++) s += d_LSE[lane + (k << 5)];
#pragma unroll
        for (int off = 16; off; off >>= 1)
            s += __shfl_xor_sync(0xffffffffu, s, off);
        if (lane == 0) lse_tot_s = s;
    }
    __syncthreads();

    if (threadIdx.x == 0) {
        float S = 0.f;
        for (int i = 0; i < 32; i++) S += terms[i];
        float ce = -(S * (1.0f / 32.0f));
        float loss = -(lse_tot_s * (1.0f / 8192.0f)) + 0.001f * ce;
        if (out_size > NOUT) out[NOUT] = loss;
    }
}

// ---------------------------------------------------------------------------
extern "C" void kernel_launch(void* const* d_in, const int* in_sizes, int n_in,
                              void* d_out, int out_size) {
    const float* Q  = (const float*)d_in[0];
    const float* K  = (const float*)d_in[1];
    const float* V  = (const float*)d_in[2];
    const float* Wq = (const float*)d_in[3];
    const float* bq = (const float*)d_in[4];
    const float* Wk = (const float*)d_in[5];
    const float* bk = (const float*)d_in[6];
    const float* Wv = (const float*)d_in[7];
    const float* bv = (const float*)d_in[8];
    const float* Wb = (const float*)d_in[9];
    const float* bb = (const float*)d_in[10];
    float* out = (float*)d_out;

    transpose_kernel<<<KF_ / 32, dim3(32, 8)>>>(K, V);
    cq_kernel<<<1024, 256>>>(Q, Wq, bq);
    ckv_kernel<<<R_ / 8, 256>>>(Wk, bk, Wv, bv);
    attn_kernel<<<256, 32>>>();
    out_kernel<<<8192, 128>>>(Wb, bb, out, out_size);
    loss_kernel<<<1, 1024>>>(out, out_size);
}